// round 3
// baseline (speedup 1.0000x reference)
#include <cuda_runtime.h>
#include <math.h>

#define BB 64
#define LL 128
#define HID 768
#define CDIM 256
#define SDIM 64
#define NOUT (CDIM + SDIM)      // 320
#define FEAT 321
#define NIT 30
#define EPSV 0.05f
#define L2E 1.4426950408889634f
#define INFN 3.0e38f

// ---------------- device scratch ---------------------------------------------
__device__ float g_Cs[BB * LL * LL];   // compact scaled cost (only [0,n)^2 valid)
__device__ float g_sq[BB * LL];
__device__ float g_rep[BB * 2 * HID];
__device__ float g_fused[BB * NOUT];
__device__ float g_sink[3 * BB];
__device__ int   g_n0[BB], g_n1[BB];

// ---------------- K_cnt: segment counts --------------------------------------
__global__ void k_cnt(const int* __restrict__ tt, const int* __restrict__ am) {
    int b = blockIdx.x, tid = threadIdx.x;  // 128
    int a = am[b * LL + tid], t = tt[b * LL + tid];
    unsigned m0 = __ballot_sync(0xffffffffu, a == 1 && t == 0);
    unsigned m1 = __ballot_sync(0xffffffffu, a == 1 && t == 1);
    __shared__ int c0[4], c1[4];
    if ((tid & 31) == 0) { c0[tid >> 5] = __popc(m0); c1[tid >> 5] = __popc(m1); }
    __syncthreads();
    if (tid == 0) {
        g_n0[b] = c0[0] + c0[1] + c0[2] + c0[3];
        g_n1[b] = c1[0] + c1[1] + c1[2] + c1[3];
    }
}

// ---------------- K_sq: row squared norms ------------------------------------
__global__ void k_sq(const float* __restrict__ H) {
    int warp = (blockIdx.x * blockDim.x + threadIdx.x) >> 5;
    int lane = threadIdx.x & 31;
    if (warp >= BB * LL) return;
    const float4* p = (const float4*)(H + (size_t)warp * HID);
    float s = 0.f;
#pragma unroll
    for (int t = 0; t < HID / 128; t++) {
        float4 v = p[lane + 32 * t];
        s += v.x * v.x + v.y * v.y + v.z * v.z + v.w * v.w;
    }
#pragma unroll
    for (int o = 16; o; o >>= 1) s += __shfl_down_sync(0xffffffffu, s, o);
    if (lane == 0) g_sq[warp] = s;
}

// ---------------- K_rep: masked means + cls -> g_rep --------------------------
__global__ void k_rep(const float* __restrict__ H, const int* __restrict__ tt,
                      const int* __restrict__ am) {
    int b = blockIdx.x;
    int tid = threadIdx.x;                 // 128
    int d = blockIdx.y * 128 + tid;        // 0..767
    __shared__ float s_m0[LL], s_m1[LL];
    {
        int a = am[b * LL + tid], t = tt[b * LL + tid];
        s_m0[tid] = (a == 1 && t == 0) ? 1.f : 0.f;
        s_m1[tid] = (a == 1 && t == 1) ? 1.f : 0.f;
    }
    __syncthreads();
    const float* Hb = H + (size_t)b * LL * HID;
    float a0 = 0.f, a1 = 0.f;
#pragma unroll 8
    for (int l = 0; l < LL; l++) {
        float h = Hb[l * HID + d];
        a0 += h * s_m0[l];
        a1 += h * s_m1[l];
    }
    float i0 = 1.f / fmaxf((float)g_n0[b], 1.f);
    float i1 = 1.f / fmaxf((float)g_n1[b], 1.f);
    g_rep[b * 2 * HID + d] = Hb[d];
    g_rep[b * 2 * HID + HID + d] = a0 * i0 - a1 * i1;
}

// ---------------- K_fused: warp-per-output matvec -----------------------------
__global__ void k_fused(const float* __restrict__ Wc, const float* __restrict__ bc,
                        const float* __restrict__ Ws, const float* __restrict__ bs,
                        const float* __restrict__ gate) {
    int w = threadIdx.x >> 5, lane = threadIdx.x & 31;
    int o = blockIdx.x * 8 + w;   // 0..319
    const float* W = (o < CDIM) ? (Wc + (size_t)o * 2 * HID)
                                : (Ws + (size_t)(o - CDIM) * 2 * HID);
    float wreg[48];
#pragma unroll
    for (int t = 0; t < 48; t++) wreg[t] = W[lane + 32 * t];
    float gv = 1.f / (1.f + expf(-gate[0]));
    float bias = (o < CDIM) ? bc[o] : bs[o - CDIM];
    float sc = (o < CDIM) ? (1.f - gv) : gv;
    for (int b = 0; b < BB; b++) {
        const float* r = g_rep + (size_t)b * 2 * HID;
        float acc = 0.f;
#pragma unroll
        for (int t = 0; t < 48; t++) acc += wreg[t] * r[lane + 32 * t];
#pragma unroll
        for (int off = 16; off; off >>= 1) acc += __shfl_down_sync(0xffffffffu, acc, off);
        if (lane == 0) g_fused[b * NOUT + o] = (acc + bias) * sc;
    }
}

// ---------------- K_gram: symmetric 32x32 tiles, active range only ------------
__global__ void k_gram(const float* __restrict__ H) {
    __constant__ static const int dummy = 0; (void)dummy;
    const int TI[10] = {0,0,0,0,1,1,1,2,2,3};
    const int TJ[10] = {0,1,2,3,1,2,3,2,3,3};
    int b = blockIdx.y;
    int n = g_n0[b] + g_n1[b];
    int t = blockIdx.x;
    int ti = TI[t], tj = TJ[t];
    int i0 = ti * 32, j0 = tj * 32;
    if (i0 >= n || j0 >= n) return;
    __shared__ __align__(16) float sA[32 * 36];
    __shared__ __align__(16) float sB[32 * 36];
    int tid = threadIdx.x;          // 64
    int tx = tid & 7, ty = tid >> 3;
    float acc[4][4] = {};
    const float* Hb = H + (size_t)b * LL * HID;
    for (int k0 = 0; k0 < HID; k0 += 32) {
#pragma unroll
        for (int q = 0; q < 4; q++) {
            int lin = tid + 64 * q;
            int row = lin >> 3, c4 = lin & 7;
            float4 v = *(const float4*)(Hb + (size_t)(i0 + row) * HID + k0 + c4 * 4);
            sA[(c4 * 4 + 0) * 36 + row] = v.x;
            sA[(c4 * 4 + 1) * 36 + row] = v.y;
            sA[(c4 * 4 + 2) * 36 + row] = v.z;
            sA[(c4 * 4 + 3) * 36 + row] = v.w;
            float4 u = *(const float4*)(Hb + (size_t)(j0 + row) * HID + k0 + c4 * 4);
            sB[(c4 * 4 + 0) * 36 + row] = u.x;
            sB[(c4 * 4 + 1) * 36 + row] = u.y;
            sB[(c4 * 4 + 2) * 36 + row] = u.z;
            sB[(c4 * 4 + 3) * 36 + row] = u.w;
        }
        __syncthreads();
#pragma unroll
        for (int kk = 0; kk < 32; kk++) {
            float4 av = *(const float4*)&sA[kk * 36 + ty * 4];
            float4 bv = *(const float4*)&sB[kk * 36 + tx * 4];
            float ar[4] = {av.x, av.y, av.z, av.w};
            float br[4] = {bv.x, bv.y, bv.z, bv.w};
#pragma unroll
            for (int r = 0; r < 4; r++)
#pragma unroll
                for (int c = 0; c < 4; c++) acc[r][c] += ar[r] * br[c];
        }
        __syncthreads();
    }
    const float* sqb = g_sq + b * LL;
    float* out = g_Cs + (size_t)b * LL * LL;
#pragma unroll
    for (int r = 0; r < 4; r++) {
        int i = i0 + ty * 4 + r;
        float si = sqb[i];
#pragma unroll
        for (int c = 0; c < 4; c++) {
            int j = j0 + tx * 4 + c;
            float d2 = si + sqb[j] - 2.f * acc[r][c];
            float v = sqrtf(fmaxf(d2, 1e-6f)) * (L2E / EPSV);
            out[i * LL + j] = v;
            if (ti != tj) out[j * LL + i] = v;
        }
    }
}

// ---------------- K_sink: compact Sinkhorn ------------------------------------
__global__ void __launch_bounds__(128) k_sink() {
    extern __shared__ float cS[];
    __shared__ __align__(16) float s_u[128], s_w[128];
    __shared__ float s_red[4];
    int bx = blockIdx.x;
    int b = bx / 3, v = bx - 3 * b;
    int n0 = g_n0[b], n1 = g_n1[b];
    int ra, na, rb, nb;
    if (v == 0)      { ra = 0;  na = n0; rb = n0; nb = n1; }
    else if (v == 1) { ra = 0;  na = n0; rb = 0;  nb = n0; }
    else             { ra = n0; na = n1; rb = n0; nb = n1; }
    int tid = threadIdx.x;
    int nbp = (nb + 3) & ~3;
    int nap = (na + 3) & ~3;
    int pitch = nbp | 1;
    // fill padded region, then gather the compact sub-block
    int tot = nap * pitch;
    for (int x = tid; x < tot; x += 128) cS[x] = INFN;
    __syncthreads();
    const float* src = g_Cs + (size_t)b * LL * LL;
    if (tid < nb) {
        for (int i = 0; i < na; i++)
            cS[i * pitch + tid] = src[(ra + i) * LL + rb + tid];
    }
    float la2 = -__log2f((float)na);
    float lb2 = -__log2f((float)nb);
    if (tid < 128) {
        s_u[tid] = (tid < nb) ? lb2 : -INFN;
        s_w[tid] = -INFN;
    }
    __syncthreads();
    float F = 0.f, G = 0.f;
    for (int it = 0; it < NIT; it++) {
        if (tid < na) {
            const float* cr = cS + tid * pitch;
            float m = -INFN;
            for (int j = 0; j < nbp; j += 4) {
                float4 u4 = *(const float4*)&s_u[j];
                float t0 = fmaxf(u4.x - cr[j],     u4.y - cr[j + 1]);
                float t1 = fmaxf(u4.z - cr[j + 2], u4.w - cr[j + 3]);
                m = fmaxf(m, fmaxf(t0, t1));
            }
            float s = 0.f;
            for (int j = 0; j < nbp; j += 4) {
                float4 u4 = *(const float4*)&s_u[j];
                s += exp2f(u4.x - cr[j] - m) + exp2f(u4.y - cr[j + 1] - m)
                   + exp2f(u4.z - cr[j + 2] - m) + exp2f(u4.w - cr[j + 3] - m);
            }
            F = -(m + __log2f(s));
        }
        __syncthreads();
        if (tid < na) s_w[tid] = la2 + F;
        __syncthreads();
        if (tid < nb) {
            float m = -INFN;
            for (int i = 0; i < nap; i += 4) {
                float4 w4 = *(const float4*)&s_w[i];
                const float* cc = cS + i * pitch + tid;
                float t0 = fmaxf(w4.x - cc[0],         w4.y - cc[pitch]);
                float t1 = fmaxf(w4.z - cc[2 * pitch], w4.w - cc[3 * pitch]);
                m = fmaxf(m, fmaxf(t0, t1));
            }
            float s = 0.f;
            for (int i = 0; i < nap; i += 4) {
                float4 w4 = *(const float4*)&s_w[i];
                const float* cc = cS + i * pitch + tid;
                s += exp2f(w4.x - cc[0] - m) + exp2f(w4.y - cc[pitch] - m)
                   + exp2f(w4.z - cc[2 * pitch] - m) + exp2f(w4.w - cc[3 * pitch] - m);
            }
            G = -(m + __log2f(s));
            s_u[tid] = lb2 + G;
        }
        __syncthreads();
    }
    float val = 0.f;
    if (tid < na) val += F * (1.f / (float)na);
    if (tid < nb) val += G * (1.f / (float)nb);
    val *= (EPSV / L2E);
#pragma unroll
    for (int o = 16; o; o >>= 1) val += __shfl_down_sync(0xffffffffu, val, o);
    if ((tid & 31) == 0) s_red[tid >> 5] = val;
    __syncthreads();
    if (tid == 0) g_sink[v * BB + b] = s_red[0] + s_red[1] + s_red[2] + s_red[3];
}

// ---------------- K_final ------------------------------------------------------
__global__ void k_final(const float* __restrict__ lnw, const float* __restrict__ lnb,
                        const float* __restrict__ Wcls, const float* __restrict__ bcls,
                        float* __restrict__ out) {
    int b = blockIdx.x, tid = threadIdx.x;  // 128
    __shared__ float s_feat[FEAT];
    __shared__ float s_r[8];
    for (int i = tid; i < FEAT; i += 128) {
        s_feat[i] = (i < NOUT)
            ? g_fused[b * NOUT + i]
            : (g_sink[b] - 0.5f * (g_sink[BB + b] + g_sink[2 * BB + b]));
    }
    __syncthreads();
    float s = 0.f, s2 = 0.f;
    for (int i = tid; i < FEAT; i += 128) {
        float x = s_feat[i];
        s += x; s2 += x * x;
    }
#pragma unroll
    for (int o = 16; o; o >>= 1) {
        s  += __shfl_down_sync(0xffffffffu, s, o);
        s2 += __shfl_down_sync(0xffffffffu, s2, o);
    }
    if ((tid & 31) == 0) { s_r[tid >> 5] = s; s_r[4 + (tid >> 5)] = s2; }
    __syncthreads();
    float S  = s_r[0] + s_r[1] + s_r[2] + s_r[3];
    float S2 = s_r[4] + s_r[5] + s_r[6] + s_r[7];
    float mu = S / (float)FEAT;
    float var = S2 / (float)FEAT - mu * mu;
    float rstd = rsqrtf(var + 1e-5f);
    float a0 = 0.f, a1 = 0.f;
    for (int i = tid; i < FEAT; i += 128) {
        float h = (s_feat[i] - mu) * rstd * lnw[i] + lnb[i];
        a0 += h * Wcls[i];
        a1 += h * Wcls[FEAT + i];
    }
#pragma unroll
    for (int o = 16; o; o >>= 1) {
        a0 += __shfl_down_sync(0xffffffffu, a0, o);
        a1 += __shfl_down_sync(0xffffffffu, a1, o);
    }
    __syncthreads();
    if ((tid & 31) == 0) { s_r[tid >> 5] = a0; s_r[4 + (tid >> 5)] = a1; }
    __syncthreads();
    if (tid == 0) {
        out[b * 2 + 0] = s_r[0] + s_r[1] + s_r[2] + s_r[3] + bcls[0];
        out[b * 2 + 1] = s_r[4] + s_r[5] + s_r[6] + s_r[7] + bcls[1];
    }
}

// ---------------- launch --------------------------------------------------------
#define SINK_SMEM (112 * 113 * 4)

extern "C" void kernel_launch(void* const* d_in, const int* in_sizes, int n_in,
                              void* d_out, int out_size) {
    const float* H    = (const float*)d_in[0];
    const int*   tt   = (const int*)d_in[1];
    const int*   am   = (const int*)d_in[2];
    const float* Wc   = (const float*)d_in[3];
    const float* bc   = (const float*)d_in[4];
    const float* Ws   = (const float*)d_in[5];
    const float* bs   = (const float*)d_in[6];
    const float* gate = (const float*)d_in[7];
    const float* lnw  = (const float*)d_in[8];
    const float* lnb  = (const float*)d_in[9];
    const float* Wcls = (const float*)d_in[10];
    const float* bcls = (const float*)d_in[11];
    float* out = (float*)d_out;

    cudaFuncSetAttribute(k_sink, cudaFuncAttributeMaxDynamicSharedMemorySize, SINK_SMEM);

    k_cnt<<<BB, 128>>>(tt, am);
    k_sq<<<(BB * LL) / 8, 256>>>(H);
    k_rep<<<dim3(BB, 6), 128>>>(H, tt, am);
    k_fused<<<40, 256>>>(Wc, bc, Ws, bs, gate);
    k_gram<<<dim3(10, BB), 64>>>(H);
    k_sink<<<3 * BB, 128, SINK_SMEM>>>();
    k_final<<<BB, 128>>>(lnw, lnb, Wcls, bcls, out);
}

// round 4
// speedup vs baseline: 1.6121x; 1.6121x over previous
#include <cuda_runtime.h>
#include <math.h>

#define BB 64
#define LL 128
#define HID 768
#define CDIM 256
#define SDIM 64
#define NOUT (CDIM + SDIM)      // 320
#define FEAT 321
#define NIT 30
#define EPSV 0.05f
#define L2E 1.4426950408889634f
#define INFN 3.0e38f

// ---------------- device scratch ---------------------------------------------
__device__ float g_Cs[BB * LL * LL];   // compact scaled cost (only [0,n)^2 valid)
__device__ float g_sq[BB * LL];
__device__ float g_rep[BB * 2 * HID];
__device__ float g_fused[BB * NOUT];
__device__ float g_sink[3 * BB];
__device__ int   g_n0[BB], g_n1[BB];

// ---------------- K_cnt: segment counts --------------------------------------
__global__ void k_cnt(const int* __restrict__ tt, const int* __restrict__ am) {
    int b = blockIdx.x, tid = threadIdx.x;  // 128
    int a = am[b * LL + tid], t = tt[b * LL + tid];
    unsigned m0 = __ballot_sync(0xffffffffu, a == 1 && t == 0);
    unsigned m1 = __ballot_sync(0xffffffffu, a == 1 && t == 1);
    __shared__ int c0[4], c1[4];
    if ((tid & 31) == 0) { c0[tid >> 5] = __popc(m0); c1[tid >> 5] = __popc(m1); }
    __syncthreads();
    if (tid == 0) {
        g_n0[b] = c0[0] + c0[1] + c0[2] + c0[3];
        g_n1[b] = c1[0] + c1[1] + c1[2] + c1[3];
    }
}

// ---------------- K_sq: row squared norms ------------------------------------
__global__ void k_sq(const float* __restrict__ H) {
    int warp = (blockIdx.x * blockDim.x + threadIdx.x) >> 5;
    int lane = threadIdx.x & 31;
    if (warp >= BB * LL) return;
    const float4* p = (const float4*)(H + (size_t)warp * HID);
    float s = 0.f;
#pragma unroll
    for (int t = 0; t < HID / 128; t++) {
        float4 v = p[lane + 32 * t];
        s += v.x * v.x + v.y * v.y + v.z * v.z + v.w * v.w;
    }
#pragma unroll
    for (int o = 16; o; o >>= 1) s += __shfl_down_sync(0xffffffffu, s, o);
    if (lane == 0) g_sq[warp] = s;
}

// ---------------- K_rep: masked means + cls -> g_rep --------------------------
__global__ void k_rep(const float* __restrict__ H, const int* __restrict__ tt,
                      const int* __restrict__ am) {
    int b = blockIdx.x;
    int tid = threadIdx.x;                 // 128
    int d = blockIdx.y * 128 + tid;        // 0..767
    __shared__ float s_m0[LL], s_m1[LL];
    {
        int a = am[b * LL + tid], t = tt[b * LL + tid];
        s_m0[tid] = (a == 1 && t == 0) ? 1.f : 0.f;
        s_m1[tid] = (a == 1 && t == 1) ? 1.f : 0.f;
    }
    __syncthreads();
    const float* Hb = H + (size_t)b * LL * HID;
    float a0 = 0.f, a1 = 0.f;
#pragma unroll 8
    for (int l = 0; l < LL; l++) {
        float h = Hb[l * HID + d];
        a0 += h * s_m0[l];
        a1 += h * s_m1[l];
    }
    float i0 = 1.f / fmaxf((float)g_n0[b], 1.f);
    float i1 = 1.f / fmaxf((float)g_n1[b], 1.f);
    g_rep[b * 2 * HID + d] = Hb[d];
    g_rep[b * 2 * HID + HID + d] = a0 * i0 - a1 * i1;
}

// ---------------- K_fused: warp-per-output, block-per-(ogroup,batch) ----------
__global__ void __launch_bounds__(256) k_fused(
        const float* __restrict__ Wc, const float* __restrict__ bc,
        const float* __restrict__ Ws, const float* __restrict__ bs,
        const float* __restrict__ gate) {
    int b = blockIdx.y;
    int w = threadIdx.x >> 5, lane = threadIdx.x & 31;
    int o = blockIdx.x * 8 + w;   // 0..319
    __shared__ __align__(16) float s_rep[2 * HID];
    const float4* g4 = (const float4*)(g_rep + (size_t)b * 2 * HID);
    float4* s4 = (float4*)s_rep;
    for (int i = threadIdx.x; i < (2 * HID) / 4; i += 256) s4[i] = g4[i];
    __syncthreads();
    const float* W = (o < CDIM) ? (Wc + (size_t)o * 2 * HID)
                                : (Ws + (size_t)(o - CDIM) * 2 * HID);
    const float4* W4 = (const float4*)W;
    const float4* r4 = (const float4*)s_rep;
    float acc = 0.f;
#pragma unroll
    for (int t = 0; t < 12; t++) {
        float4 wv = W4[lane + 32 * t];
        float4 rv = r4[lane + 32 * t];
        acc += wv.x * rv.x + wv.y * rv.y + wv.z * rv.z + wv.w * rv.w;
    }
#pragma unroll
    for (int off = 16; off; off >>= 1) acc += __shfl_down_sync(0xffffffffu, acc, off);
    if (lane == 0) {
        float gv = 1.f / (1.f + expf(-gate[0]));
        float bias = (o < CDIM) ? bc[o] : bs[o - CDIM];
        float sc = (o < CDIM) ? (1.f - gv) : gv;
        g_fused[b * NOUT + o] = (acc + bias) * sc;
    }
}

// ---------------- K_gram: symmetric 32x32 tiles, active range only ------------
__global__ void k_gram(const float* __restrict__ H) {
    const int TI[10] = {0,0,0,0,1,1,1,2,2,3};
    const int TJ[10] = {0,1,2,3,1,2,3,2,3,3};
    int b = blockIdx.y;
    int n = g_n0[b] + g_n1[b];
    int t = blockIdx.x;
    int ti = TI[t], tj = TJ[t];
    int i0 = ti * 32, j0 = tj * 32;
    if (i0 >= n || j0 >= n) return;
    __shared__ __align__(16) float sA[32 * 36];
    __shared__ __align__(16) float sB[32 * 36];
    int tid = threadIdx.x;          // 64
    int tx = tid & 7, ty = tid >> 3;
    float acc[4][4] = {};
    const float* Hb = H + (size_t)b * LL * HID;
    for (int k0 = 0; k0 < HID; k0 += 32) {
#pragma unroll
        for (int q = 0; q < 4; q++) {
            int lin = tid + 64 * q;
            int row = lin >> 3, c4 = lin & 7;
            float4 v = *(const float4*)(Hb + (size_t)(i0 + row) * HID + k0 + c4 * 4);
            sA[(c4 * 4 + 0) * 36 + row] = v.x;
            sA[(c4 * 4 + 1) * 36 + row] = v.y;
            sA[(c4 * 4 + 2) * 36 + row] = v.z;
            sA[(c4 * 4 + 3) * 36 + row] = v.w;
            float4 u = *(const float4*)(Hb + (size_t)(j0 + row) * HID + k0 + c4 * 4);
            sB[(c4 * 4 + 0) * 36 + row] = u.x;
            sB[(c4 * 4 + 1) * 36 + row] = u.y;
            sB[(c4 * 4 + 2) * 36 + row] = u.z;
            sB[(c4 * 4 + 3) * 36 + row] = u.w;
        }
        __syncthreads();
#pragma unroll
        for (int kk = 0; kk < 32; kk++) {
            float4 av = *(const float4*)&sA[kk * 36 + ty * 4];
            float4 bv = *(const float4*)&sB[kk * 36 + tx * 4];
            float ar[4] = {av.x, av.y, av.z, av.w};
            float br[4] = {bv.x, bv.y, bv.z, bv.w};
#pragma unroll
            for (int r = 0; r < 4; r++)
#pragma unroll
                for (int c = 0; c < 4; c++) acc[r][c] += ar[r] * br[c];
        }
        __syncthreads();
    }
    const float* sqb = g_sq + b * LL;
    float* out = g_Cs + (size_t)b * LL * LL;
#pragma unroll
    for (int r = 0; r < 4; r++) {
        int i = i0 + ty * 4 + r;
        float si = sqb[i];
#pragma unroll
        for (int c = 0; c < 4; c++) {
            int j = j0 + tx * 4 + c;
            float d2 = si + sqb[j] - 2.f * acc[r][c];
            float v = sqrtf(fmaxf(d2, 1e-6f)) * (L2E / EPSV);
            out[i * LL + j] = v;
            if (ti != tj) out[j * LL + i] = v;
        }
    }
}

// ---------------- K_sink: compact Sinkhorn ------------------------------------
__global__ void __launch_bounds__(128) k_sink() {
    extern __shared__ float cS[];
    __shared__ __align__(16) float s_u[128], s_w[128];
    __shared__ float s_red[4];
    int bx = blockIdx.x;
    int b = bx / 3, v = bx - 3 * b;
    int n0 = g_n0[b], n1 = g_n1[b];
    int ra, na, rb, nb;
    if (v == 0)      { ra = 0;  na = n0; rb = n0; nb = n1; }
    else if (v == 1) { ra = 0;  na = n0; rb = 0;  nb = n0; }
    else             { ra = n0; na = n1; rb = n0; nb = n1; }
    int tid = threadIdx.x;
    int nbp = (nb + 3) & ~3;
    int nap = (na + 3) & ~3;
    int pitch = nbp | 1;
    int tot = nap * pitch;
    for (int x = tid; x < tot; x += 128) cS[x] = INFN;
    __syncthreads();
    const float* src = g_Cs + (size_t)b * LL * LL;
    if (tid < nb) {
        for (int i = 0; i < na; i++)
            cS[i * pitch + tid] = src[(ra + i) * LL + rb + tid];
    }
    float la2 = -__log2f((float)na);
    float lb2 = -__log2f((float)nb);
    s_u[tid] = (tid < nb) ? lb2 : -INFN;
    s_w[tid] = -INFN;
    __syncthreads();
    float F = 0.f, G = 0.f;
    for (int it = 0; it < NIT; it++) {
        if (tid < na) {
            const float* cr = cS + tid * pitch;
            float m = -INFN;
            for (int j = 0; j < nbp; j += 4) {
                float4 u4 = *(const float4*)&s_u[j];
                float t0 = fmaxf(u4.x - cr[j],     u4.y - cr[j + 1]);
                float t1 = fmaxf(u4.z - cr[j + 2], u4.w - cr[j + 3]);
                m = fmaxf(m, fmaxf(t0, t1));
            }
            float s = 0.f;
            for (int j = 0; j < nbp; j += 4) {
                float4 u4 = *(const float4*)&s_u[j];
                s += exp2f(u4.x - cr[j] - m) + exp2f(u4.y - cr[j + 1] - m)
                   + exp2f(u4.z - cr[j + 2] - m) + exp2f(u4.w - cr[j + 3] - m);
            }
            F = -(m + __log2f(s));
        }
        __syncthreads();
        if (tid < na) s_w[tid] = la2 + F;
        __syncthreads();
        if (tid < nb) {
            float m = -INFN;
            for (int i = 0; i < nap; i += 4) {
                float4 w4 = *(const float4*)&s_w[i];
                const float* cc = cS + i * pitch + tid;
                float t0 = fmaxf(w4.x - cc[0],         w4.y - cc[pitch]);
                float t1 = fmaxf(w4.z - cc[2 * pitch], w4.w - cc[3 * pitch]);
                m = fmaxf(m, fmaxf(t0, t1));
            }
            float s = 0.f;
            for (int i = 0; i < nap; i += 4) {
                float4 w4 = *(const float4*)&s_w[i];
                const float* cc = cS + i * pitch + tid;
                s += exp2f(w4.x - cc[0] - m) + exp2f(w4.y - cc[pitch] - m)
                   + exp2f(w4.z - cc[2 * pitch] - m) + exp2f(w4.w - cc[3 * pitch] - m);
            }
            G = -(m + __log2f(s));
            s_u[tid] = lb2 + G;
        }
        __syncthreads();
    }
    float val = 0.f;
    if (tid < na) val += F * (1.f / (float)na);
    if (tid < nb) val += G * (1.f / (float)nb);
    val *= (EPSV / L2E);
#pragma unroll
    for (int o = 16; o; o >>= 1) val += __shfl_down_sync(0xffffffffu, val, o);
    if ((tid & 31) == 0) s_red[tid >> 5] = val;
    __syncthreads();
    if (tid == 0) g_sink[v * BB + b] = s_red[0] + s_red[1] + s_red[2] + s_red[3];
}

// ---------------- K_final ------------------------------------------------------
__global__ void k_final(const float* __restrict__ lnw, const float* __restrict__ lnb,
                        const float* __restrict__ Wcls, const float* __restrict__ bcls,
                        float* __restrict__ out) {
    int b = blockIdx.x, tid = threadIdx.x;  // 128
    __shared__ float s_feat[FEAT];
    __shared__ float s_r[8];
    for (int i = tid; i < FEAT; i += 128) {
        s_feat[i] = (i < NOUT)
            ? g_fused[b * NOUT + i]
            : (g_sink[b] - 0.5f * (g_sink[BB + b] + g_sink[2 * BB + b]));
    }
    __syncthreads();
    float s = 0.f, s2 = 0.f;
    for (int i = tid; i < FEAT; i += 128) {
        float x = s_feat[i];
        s += x; s2 += x * x;
    }
#pragma unroll
    for (int o = 16; o; o >>= 1) {
        s  += __shfl_down_sync(0xffffffffu, s, o);
        s2 += __shfl_down_sync(0xffffffffu, s2, o);
    }
    if ((tid & 31) == 0) { s_r[tid >> 5] = s; s_r[4 + (tid >> 5)] = s2; }
    __syncthreads();
    float S  = s_r[0] + s_r[1] + s_r[2] + s_r[3];
    float S2 = s_r[4] + s_r[5] + s_r[6] + s_r[7];
    float mu = S / (float)FEAT;
    float var = S2 / (float)FEAT - mu * mu;
    float rstd = rsqrtf(var + 1e-5f);
    float a0 = 0.f, a1 = 0.f;
    for (int i = tid; i < FEAT; i += 128) {
        float h = (s_feat[i] - mu) * rstd * lnw[i] + lnb[i];
        a0 += h * Wcls[i];
        a1 += h * Wcls[FEAT + i];
    }
#pragma unroll
    for (int o = 16; o; o >>= 1) {
        a0 += __shfl_down_sync(0xffffffffu, a0, o);
        a1 += __shfl_down_sync(0xffffffffu, a1, o);
    }
    __syncthreads();
    if ((tid & 31) == 0) { s_r[tid >> 5] = a0; s_r[4 + (tid >> 5)] = a1; }
    __syncthreads();
    if (tid == 0) {
        out[b * 2 + 0] = s_r[0] + s_r[1] + s_r[2] + s_r[3] + bcls[0];
        out[b * 2 + 1] = s_r[4] + s_r[5] + s_r[6] + s_r[7] + bcls[1];
    }
}

// ---------------- launch --------------------------------------------------------
#define SINK_SMEM (112 * 113 * 4)

extern "C" void kernel_launch(void* const* d_in, const int* in_sizes, int n_in,
                              void* d_out, int out_size) {
    const float* H    = (const float*)d_in[0];
    const int*   tt   = (const int*)d_in[1];
    const int*   am   = (const int*)d_in[2];
    const float* Wc   = (const float*)d_in[3];
    const float* bc   = (const float*)d_in[4];
    const float* Ws   = (const float*)d_in[5];
    const float* bs   = (const float*)d_in[6];
    const float* gate = (const float*)d_in[7];
    const float* lnw  = (const float*)d_in[8];
    const float* lnb  = (const float*)d_in[9];
    const float* Wcls = (const float*)d_in[10];
    const float* bcls = (const float*)d_in[11];
    float* out = (float*)d_out;

    cudaFuncSetAttribute(k_sink, cudaFuncAttributeMaxDynamicSharedMemorySize, SINK_SMEM);

    k_cnt<<<BB, 128>>>(tt, am);
    k_sq<<<(BB * LL) / 8, 256>>>(H);
    k_rep<<<dim3(BB, 6), 128>>>(H, tt, am);
    k_fused<<<dim3(40, BB), 256>>>(Wc, bc, Ws, bs, gate);
    k_gram<<<dim3(10, BB), 64>>>(H);
    k_sink<<<3 * BB, 128, SINK_SMEM>>>();
    k_final<<<BB, 128>>>(lnw, lnb, Wcls, bcls, out);
}